// round 11
// baseline (speedup 1.0000x reference)
#include <cuda_runtime.h>
#include <cuda_bf16.h>
#include <cstdint>

#define T_ 64
#define B_ 128
#define L_ 64
#define E_ 256
#define H_ 32
#define N_ (T_*B_)

// ---- attn SMEM layout (bytes); 2 n per block -> 128 X rows ----
#define XROW 528
#define XH_OFF   0                    // 128 x 528
#define XL_OFF   67584
#define AT_OFF   135168               // 2 bufs x (hi 12288 + lo 12288)
#define AT_BUF   24576
#define AT_LO    12288
#define YC_OFF   184320               // 2 bufs x (hi 10240 + lo 10240), row stride 80
#define YC_BUF   20480
#define YC_LO    10240
#define PROB_OFF AT_OFF               // reuse: 128 x 68 f32 = 34816 (< 49152)
#define DROPF_OFF 225280              // 128 f32
#define WSUM_OFF  225792              // 128 f32
#define RINV_OFF  226304              // 128 f32
#define ZSH_OFF   226816              // 512 f32
#define ATTN_SMEM 228864

__device__ __nv_bfloat16 g_At_hi[E_*E_];
__device__ __nv_bfloat16 g_At_lo[E_*E_];
__device__ float g_Ccm[E_*E_];
__device__ float g_M[E_*128];               // M[j][g] = sum_f Ccm[j][f]*w_ih[g][f]
__device__ float g_xw[(size_t)N_*128];
__device__ int   g_mask_mode;

// ---------------- helpers ----------------
__device__ __forceinline__ uint32_t smem_u32(const void* p) {
    uint32_t a;
    asm("{ .reg .u64 t; cvta.to.shared.u64 t, %1; cvt.u32.u64 %0, t; }"
        : "=r"(a) : "l"(p));
    return a;
}
__device__ __forceinline__ uint32_t lds32(uint32_t a) {
    uint32_t v;
    asm volatile("ld.shared.b32 %0, [%1];" : "=r"(v) : "r"(a));
    return v;
}
__device__ __forceinline__ void sts32(uint32_t a, uint32_t v) {
    asm volatile("st.shared.b32 [%0], %1;" :: "r"(a), "r"(v));
}
__device__ __forceinline__ void sts64(uint32_t a, uint32_t v0, uint32_t v1) {
    asm volatile("st.shared.v2.b32 [%0], {%1, %2};" :: "r"(a), "r"(v0), "r"(v1));
}
#define CP_ASYNC16(dst, src) \
    asm volatile("cp.async.ca.shared.global [%0], [%1], 16;" :: "r"(dst), "l"(src))
#define CP_COMMIT() asm volatile("cp.async.commit_group;" ::: "memory")
#define CP_WAIT0()  asm volatile("cp.async.wait_group 0;" ::: "memory")

// D += A * B^T  (m16n8k16, bf16 in, f32 accum)
__device__ __forceinline__ void mma16816(float* d, const uint32_t* a, const uint32_t* b) {
    asm volatile(
        "mma.sync.aligned.m16n8k16.row.col.f32.bf16.bf16.f32 "
        "{%0,%1,%2,%3}, {%4,%5,%6,%7}, {%8,%9}, {%0,%1,%2,%3};"
        : "+f"(d[0]), "+f"(d[1]), "+f"(d[2]), "+f"(d[3])
        : "r"(a[0]), "r"(a[1]), "r"(a[2]), "r"(a[3]), "r"(b[0]), "r"(b[1]));
}

__device__ __forceinline__ uint32_t pack_hi(float a, float b, float& ra, float& rb) {
    __nv_bfloat162 t = __floats2bfloat162_rn(a, b);
    ra = a - __low2float(t);
    rb = b - __high2float(t);
    return *(uint32_t*)&t;
}
__device__ __forceinline__ uint32_t pack_lo(float a, float b) {
    __nv_bfloat162 t = __floats2bfloat162_rn(a, b);
    return *(uint32_t*)&t;
}

// ---------------------------------------------------------------------------
__global__ void detect_mask_kernel(const void* __restrict__ mask)
{
    const unsigned int* w = (const unsigned int*)mask;
    __shared__ int s_not01, s_notf;
    if (threadIdx.x == 0) { s_not01 = 0; s_notf = 0; }
    __syncthreads();
    int not01 = 0, notf = 0;
    for (int i = threadIdx.x; i < 131072; i += 256) {
        unsigned int v = w[i];
        if (v != 0u && v != 1u) not01 = 1;
        if (v != 0u && v != 0x3F800000u) notf = 1;
    }
    if (not01) atomicOr(&s_not01, 1);
    if (notf)  atomicOr(&s_notf, 1);
    __syncthreads();
    if (threadIdx.x == 0)
        g_mask_mode = (!s_not01) ? 1 : ((!s_notf) ? 2 : 0);
}

// blocks [0,256): At[j][e] = sum_f Wq[f,e]*Wk[f,j] -> bf16 hi/lo
// blocks [256,512): Ccm[j][f] = (Wout@Wv)[f][j]
__global__ __launch_bounds__(256) void precompute_kernel(
    const float* __restrict__ in_proj, const float* __restrict__ out_proj)
{
    __shared__ float buf[E_];
    const int b = blockIdx.x, tid = threadIdx.x;
    if (b < E_) {
        const int j = b;
        float acc = 0.f;
        #pragma unroll 4
        for (int f = 0; f < E_; ++f)
            acc = fmaf(in_proj[f*E_ + tid], in_proj[(E_+f)*E_ + j], acc);
        __nv_bfloat16 h = __float2bfloat16_rn(acc);
        g_At_hi[j*E_ + tid] = h;
        g_At_lo[j*E_ + tid] = __float2bfloat16_rn(acc - __bfloat162float(h));
    } else {
        const int f = b - E_;
        buf[tid] = out_proj[f*E_ + tid];
        __syncthreads();
        float acc = 0.f;
        #pragma unroll 4
        for (int e = 0; e < E_; ++e)
            acc = fmaf(buf[e], in_proj[(2*E_+e)*E_ + tid], acc);
        g_Ccm[tid*E_ + f] = acc;
    }
}

// M[j][g] = sum_f Ccm[j][f] * w_ih[g][f]    (grid 256 = j, 128 thr = g)
__global__ __launch_bounds__(128) void precompute2_kernel(const float* __restrict__ w_ih)
{
    __shared__ float cj[E_];
    const int j = blockIdx.x, tid = threadIdx.x;
    cj[tid]       = g_Ccm[j*E_ + tid];
    cj[tid + 128] = g_Ccm[j*E_ + tid + 128];
    __syncthreads();
    float acc = 0.f;
    #pragma unroll 4
    for (int f = 0; f < E_; ++f)
        acc = fmaf(cj[f], w_ih[tid*E_ + f], acc);
    g_M[j*128 + tid] = acc;
}

// ---------------------------------------------------------------------------
// Attention: 2 rows n per block, 512 threads (16 warps), HMMA bf16-split,
// GEMM2 fused chunk-wise to keep Y in registers.
__global__ __launch_bounds__(512, 1) void attn_mma_kernel(
    const float* __restrict__ x, const void* __restrict__ mask)
{
    extern __shared__ char sm[];
    const uint32_t sb = smem_u32(sm);
    const int tid = threadIdx.x;
    const int w = tid >> 5, lane = tid & 31;
    const int qr = lane >> 2, qc = lane & 3;
    const int mt = w & 7, m0 = mt * 16;     // m-tile (16 of 128 rows)
    const int nh = w >> 3;                  // GEMM1 n-half (128 cols each)
    const int nhalf = nh << 7;
    const int nlw = mt >> 2;                // which n this warp's rows belong to
    const int n0 = blockIdx.x * 2;

    float* dropf  = (float*)(sm + DROPF_OFF);
    float* wsm    = (float*)(sm + WSUM_OFF);
    float* rowinv = (float*)(sm + RINV_OFF);
    float* zsh    = (float*)(sm + ZSH_OFF);

    // --- prologue: issue At chunk 0 (overlaps X load/split) ---
    {
        int j = tid >> 1, half = tid & 1;
        uint32_t d = sb + AT_OFF + j*48 + half*16;
        CP_ASYNC16(d,         g_At_hi + j*E_ + half*8);
        CP_ASYNC16(d + AT_LO, g_At_lo + j*E_ + half*8);
    }
    CP_COMMIT();

    // --- mask + wsum init (128 local rows = 2 n x 64 L) ---
    if (tid < 128) {
        int mode = g_mask_mode;
        size_t idx = (size_t)(n0 + (tid >> 6)) * L_ + (tid & 63);
        bool obs;
        if (mode == 1)      obs = ((const int*)mask)[idx] != 0;
        else if (mode == 2) obs = ((const float*)mask)[idx] != 0.0f;
        else                obs = ((const unsigned char*)mask)[idx] != 0;
        dropf[tid] = obs ? 0.f : 1.f;
        wsm[tid] = 0.f;
    }

    // --- load X (128 rows x 256 f32), split to bf16 hi/lo ---
    {
        const float4* xg = (const float4*)(x + (size_t)n0 * (L_*E_));
        for (int i = tid; i < 8192; i += 512) {
            float4 v = xg[i];
            int row = i >> 6, c4 = i & 63;
            float la, lb, lc, ld;
            uint32_t h01 = pack_hi(v.x, v.y, la, lb);
            uint32_t h23 = pack_hi(v.z, v.w, lc, ld);
            uint32_t l01 = pack_lo(la, lb);
            uint32_t l23 = pack_lo(lc, ld);
            uint32_t o = row*XROW + c4*8;
            sts64(sb + XH_OFF + o, h01, h23);
            sts64(sb + XL_OFF + o, l01, l23);
        }
    }

    // ===== GEMM1: Y[128,256] = Xsplit @ At^T, K=256 in 16 chunks =====
    float acc[16][4];
    #pragma unroll
    for (int t = 0; t < 16; ++t)
        #pragma unroll
        for (int r = 0; r < 4; ++r) acc[t][r] = 0.f;

    const uint32_t xh_a = sb + XH_OFF + (m0+qr)*XROW + qc*4;
    const uint32_t xl_a = xh_a + (XL_OFF - XH_OFF);

    #pragma unroll 1
    for (int k = 0; k < 16; ++k) {
        CP_WAIT0();
        __syncthreads();
        if (k < 15) {
            int e0 = (k+1)*16;
            uint32_t dst = sb + AT_OFF + ((k+1) & 1)*AT_BUF;
            int j = tid >> 1, half = tid & 1;
            uint32_t d = dst + j*48 + half*16;
            CP_ASYNC16(d,         g_At_hi + j*E_ + e0 + half*8);
            CP_ASYNC16(d + AT_LO, g_At_lo + j*E_ + e0 + half*8);
            CP_COMMIT();
        }
        const uint32_t atb = sb + AT_OFF + (k & 1)*AT_BUF;
        const uint32_t e2 = (uint32_t)k * 32;
        uint32_t a_h[4], a_l[4];
        a_h[0] = lds32(xh_a + e2);
        a_h[1] = lds32(xh_a + e2 + 8*XROW);
        a_h[2] = lds32(xh_a + e2 + 16);
        a_h[3] = lds32(xh_a + e2 + 8*XROW + 16);
        a_l[0] = lds32(xl_a + e2);
        a_l[1] = lds32(xl_a + e2 + 8*XROW);
        a_l[2] = lds32(xl_a + e2 + 16);
        a_l[3] = lds32(xl_a + e2 + 8*XROW + 16);
        #pragma unroll
        for (int nt = 0; nt < 16; ++nt) {
            uint32_t ba = atb + (uint32_t)(nhalf + nt*8 + qr)*48 + qc*4;
            uint32_t bh[2] = { lds32(ba),         lds32(ba + 16) };
            uint32_t bl[2] = { lds32(ba + AT_LO), lds32(ba + AT_LO + 16) };
            mma16816(acc[nt], a_h, bh);
            mma16816(acc[nt], a_h, bl);
            mma16816(acc[nt], a_l, bh);
        }
    }

    // ===== GEMM2 (fused): S[128,64] = Ysplit @ Xsplit^T, 8 j-chunks of 32 =====
    float s2[4][4];
    #pragma unroll
    for (int t = 0; t < 4; ++t)
        #pragma unroll
        for (int r = 0; r < 4; ++r) s2[t][r] = 0.f;

    const uint32_t nbK = (uint32_t)(nlw*64 + nh*32);

    #pragma unroll 1
    for (int c = 0; c < 8; ++c) {
        const uint32_t ycb = sb + YC_OFF + (c & 1)*YC_BUF;
        if (nh == (c >> 2)) {
            int ntg = (c & 3) * 4;
            #pragma unroll
            for (int q = 0; q < 4; ++q) {
                int nt = ntg + q;
                float r0, r1, r2, r3;
                uint32_t h01 = pack_hi(acc[nt][0], acc[nt][1], r0, r1);
                uint32_t l01 = pack_lo(r0, r1);
                uint32_t h23 = pack_hi(acc[nt][2], acc[nt][3], r2, r3);
                uint32_t l23 = pack_lo(r2, r3);
                uint32_t a0 = ycb + (uint32_t)(m0+qr)*80 + q*16 + qc*4;
                sts32(a0, h01);
                sts32(a0 + 8*80, h23);
                sts32(a0 + YC_LO, l01);
                sts32(a0 + YC_LO + 8*80, l23);
            }
        }
        __syncthreads();
        #pragma unroll
        for (int ki = 0; ki < 2; ++ki) {
            uint32_t ya = ycb + (uint32_t)(m0+qr)*80 + ki*32 + qc*4;
            uint32_t a_h[4], a_l[4];
            a_h[0] = lds32(ya);
            a_h[1] = lds32(ya + 8*80);
            a_h[2] = lds32(ya + 16);
            a_h[3] = lds32(ya + 8*80 + 16);
            a_l[0] = lds32(ya + YC_LO);
            a_l[1] = lds32(ya + YC_LO + 8*80);
            a_l[2] = lds32(ya + YC_LO + 16);
            a_l[3] = lds32(ya + YC_LO + 8*80 + 16);
            uint32_t j2 = (uint32_t)(c*64 + ki*32);
            #pragma unroll
            for (int nt2 = 0; nt2 < 4; ++nt2) {
                uint32_t ba = sb + XH_OFF + (nbK + nt2*8 + qr)*XROW + j2 + qc*4;
                uint32_t bh[2] = { lds32(ba), lds32(ba + 16) };
                uint32_t bl[2] = { lds32(ba + (XL_OFF - XH_OFF)),
                                   lds32(ba + (XL_OFF - XH_OFF) + 16) };
                mma16816(s2[nt2], a_h, bh);
                mma16816(s2[nt2], a_h, bl);
                mma16816(s2[nt2], a_l, bh);
            }
        }
    }

    // --- scale + mask, dump S to probs (128 rows x 64 cols, stride 68) ---
    {
        float* probs = (float*)(sm + PROB_OFF);
        int r0i = m0 + qr, r1i = r0i + 8;
        float dl0 = dropf[r0i], dl1 = dropf[r1i];
        #pragma unroll
        for (int nt2 = 0; nt2 < 4; ++nt2) {
            int c0 = nh*32 + nt2*8 + qc*2;
            float dk0 = dropf[nlw*64 + c0], dk1 = dropf[nlw*64 + c0 + 1];
            float v00 = s2[nt2][0] * 0.0625f;
            float v01 = s2[nt2][1] * 0.0625f;
            float v10 = s2[nt2][2] * 0.0625f;
            float v11 = s2[nt2][3] * 0.0625f;
            if (dl0 != 0.f && dk0 != 0.f) v00 = -1e9f;
            if (dl0 != 0.f && dk1 != 0.f) v01 = -1e9f;
            if (dl1 != 0.f && dk0 != 0.f) v10 = -1e9f;
            if (dl1 != 0.f && dk1 != 0.f) v11 = -1e9f;
            probs[r0i*68 + c0]     = v00;
            probs[r0i*68 + c0 + 1] = v01;
            probs[r1i*68 + c0]     = v10;
            probs[r1i*68 + c0 + 1] = v11;
        }
    }
    __syncthreads();

    // --- softmax over k (4 lanes per row, 128 rows) ---
    {
        float* probs = (float*)(sm + PROB_OFF);
        int r = tid >> 2, part = tid & 3;
        float* Srow = probs + r*68 + (part << 4);
        float m = -1e30f;
        #pragma unroll
        for (int kk = 0; kk < 16; ++kk) m = fmaxf(m, Srow[kk]);
        m = fmaxf(m, __shfl_xor_sync(0xffffffffu, m, 1));
        m = fmaxf(m, __shfl_xor_sync(0xffffffffu, m, 2));
        float ssum = 0.f;
        #pragma unroll
        for (int kk = 0; kk < 16; ++kk) {
            float p = __expf(Srow[kk] - m);
            Srow[kk] = p; ssum += p;
        }
        ssum += __shfl_xor_sync(0xffffffffu, ssum, 1);
        ssum += __shfl_xor_sync(0xffffffffu, ssum, 2);
        if (part == 0) rowinv[r] = 1.f / ssum;
    }
    __syncthreads();

    // --- column sums of probs ---
    if (tid < 256) {
        float* probs = (float*)(sm + PROB_OFF);
        int nl = tid >> 7, k = tid & 63, seg = (tid >> 6) & 1;
        float p = 0.f;
        #pragma unroll
        for (int li = 0; li < 32; ++li) {
            int r = nl*64 + seg*32 + li;
            p = fmaf(probs[r*68 + k], rowinv[r], p);
        }
        atomicAdd(&wsm[nl*64 + k], p);
    }
    __syncthreads();

    // --- z[nl][e] = sum_k w[k] * x[k][e]  (x = hi + lo) ---
    {
        const __nv_bfloat16* xh = (const __nv_bfloat16*)(sm + XH_OFF);
        const __nv_bfloat16* xl = (const __nv_bfloat16*)(sm + XL_OFF);
        int nl = tid >> 8, e = tid & 255;
        float z = 0.f;
        #pragma unroll 8
        for (int k = 0; k < 64; ++k) {
            int row = nl*64 + k;
            float xv = __bfloat162float(xh[row*(XROW/2) + e]) +
                       __bfloat162float(xl[row*(XROW/2) + e]);
            z = fmaf(wsm[nl*64 + k], xv, z);
        }
        zsh[nl*256 + e] = z;
    }
    __syncthreads();

    // --- xw[nl][g] = sum_j z[nl][j] * M[j][g]  -> g_xw ---
    if (tid < 256) {
        int nl = tid >> 7, g = tid & 127;
        const float* zp = zsh + nl*256;
        float acc2 = 0.f;
        #pragma unroll 4
        for (int j = 0; j < E_; ++j)
            acc2 = fmaf(zp[j], g_M[j*128 + g], acc2);
        g_xw[(size_t)(n0 + nl)*128 + g] = acc2;
    }
}

// ---------------------------------------------------------------------------
// LSTM + critic: one block per env, xw precomputed, only h@w_hh serial.
__global__ __launch_bounds__(128) void lstm_kernel(
    const float* __restrict__ done, const float* __restrict__ h0,
    const float* __restrict__ c0,
    const float* __restrict__ w_hh,
    const float* __restrict__ b_ih, const float* __restrict__ b_hh,
    const float* __restrict__ critic_w, const float* __restrict__ critic_b,
    float* __restrict__ out)
{
    __shared__ float whh[128*36];
    __shared__ float bias[128];
    __shared__ float garr[128];
    __shared__ float hsm[32];
    __shared__ float csm[32];

    const int env = blockIdx.x, tid = threadIdx.x;

    for (int i = tid; i < 128*32; i += 128)
        whh[(i >> 5)*36 + (i & 31)] = w_hh[i];
    bias[tid] = b_ih[tid] + b_hh[tid];
    if (tid < 32) { hsm[tid] = h0[env*H_ + tid]; csm[tid] = c0[env*H_ + tid]; }
    const float cw = (tid < 32) ? critic_w[tid] : 0.f;
    const float cb = critic_b[0];
    __syncthreads();

    const float4* wh = (const float4*)(whh + tid*36);
    float xcur = g_xw[(size_t)env*128 + tid];
    float dcur = done[env];

    for (int t = 0; t < T_; ++t) {
        float xnxt = 0.f, dnxt = 0.f;
        if (t < T_ - 1) {
            int nr = (t+1)*B_ + env;
            xnxt = g_xw[(size_t)nr*128 + tid];
            dnxt = done[nr];
        }
        const float keep = 1.f - dcur;
        if (tid < 32) { hsm[tid] *= keep; csm[tid] *= keep; }
        __syncthreads();

        float acc = bias[tid] + xcur;
        const float4* hv = (const float4*)hsm;
        #pragma unroll
        for (int j4 = 0; j4 < 8; ++j4) {
            float4 a = wh[j4], b = hv[j4];
            acc = fmaf(a.x, b.x, acc); acc = fmaf(a.y, b.y, acc);
            acc = fmaf(a.z, b.z, acc); acc = fmaf(a.w, b.w, acc);
        }
        garr[tid] = (tid >= 64 && tid < 96) ? tanhf(acc)
                                            : (1.f / (1.f + __expf(-acc)));
        __syncthreads();

        if (tid < 32) {
            float c = fmaf(garr[32 + tid], csm[tid], garr[tid] * garr[64 + tid]);
            float h = garr[96 + tid] * tanhf(c);
            csm[tid] = c; hsm[tid] = h;
            float p = h * cw;
            p += __shfl_xor_sync(0xffffffffu, p, 16);
            p += __shfl_xor_sync(0xffffffffu, p, 8);
            p += __shfl_xor_sync(0xffffffffu, p, 4);
            p += __shfl_xor_sync(0xffffffffu, p, 2);
            p += __shfl_xor_sync(0xffffffffu, p, 1);
            if (tid == 0) out[t*B_ + env] = p + cb;
        }
        xcur = xnxt; dcur = dnxt;
    }
}

extern "C" void kernel_launch(void* const* d_in, const int* in_sizes, int n_in,
                              void* d_out, int out_size)
{
    const float* x        = (const float*)d_in[0];
    const float* done     = (const float*)d_in[1];
    const void*  mask     = d_in[2];
    const float* h0       = (const float*)d_in[3];
    const float* c0       = (const float*)d_in[4];
    const float* in_proj  = (const float*)d_in[5];
    const float* out_proj = (const float*)d_in[6];
    const float* w_ih     = (const float*)d_in[7];
    const float* w_hh     = (const float*)d_in[8];
    const float* b_ih     = (const float*)d_in[9];
    const float* b_hh     = (const float*)d_in[10];
    const float* critic_w = (const float*)d_in[11];
    const float* critic_b = (const float*)d_in[12];
    float* out = (float*)d_out;

    cudaFuncSetAttribute(attn_mma_kernel, cudaFuncAttributeMaxDynamicSharedMemorySize, ATTN_SMEM);

    detect_mask_kernel<<<1, 256>>>(mask);
    precompute_kernel<<<2*E_, 256>>>(in_proj, out_proj);
    precompute2_kernel<<<E_, 128>>>(w_ih);
    attn_mma_kernel<<<N_/2, 512, ATTN_SMEM>>>(x, mask);
    lstm_kernel<<<B_, 128>>>(done, h0, c0, w_hh, b_ih, b_hh,
                             critic_w, critic_b, out);
}